// round 1
// baseline (speedup 1.0000x reference)
#include <cuda_runtime.h>
#include <math.h>

// Problem shapes (fixed for this dataset entry)
#define T_TOK 16384      // B*S
#define DIM   2048       // D
#define EXP   64         // E
#define NTOT  128        // gate(64) + noise(64) projection outputs

// GEMM tiling
#define BM 128
#define BN 128
#define BK 16
#define LDA (BM + 4)
#define LDB (BN + 4)

// Epilogue config
#define EPI_BLOCKS 256
#define EPI_WARPS  8
#define TOK_PER_WARP (T_TOK / (EPI_BLOCKS * EPI_WARPS))   // 8

// Scratch (static __device__ arrays: allocation-free per harness rules)
__device__ float g_proj[(size_t)T_TOK * NTOT];            // 8 MB: [t][0:64]=gate logits, [64:128]=noise proj
__device__ float g_psum[EPI_BLOCKS * EXP];                // per-block router-prob partial sums
__device__ float g_cnt [EPI_BLOCKS * EXP];                // per-block indicator counts

// ---- Blackwell packed f32x2 helpers -------------------------------------
__device__ __forceinline__ unsigned long long pk2(float lo, float hi) {
    unsigned long long r;
    asm("mov.b64 %0, {%1, %2};" : "=l"(r) : "f"(lo), "f"(hi));
    return r;
}
__device__ __forceinline__ void fma2(unsigned long long &d,
                                     unsigned long long a,
                                     unsigned long long b) {
    asm("fma.rn.f32x2 %0, %1, %2, %0;" : "+l"(d) : "l"(a), "l"(b));
}

// ---- Kernel A: fused dual-projection GEMM (fp32, f32x2 packed FMA) ------
// C[t, n] = sum_d x[t,d] * W[n,d],  W rows 0..63 = W_gate, 64..127 = W_noise
__global__ __launch_bounds__(256, 1) void gemm_kernel(
    const float* __restrict__ x,
    const float* __restrict__ Wg,
    const float* __restrict__ Wn)
{
    __shared__ __align__(16) float As[2][BK][LDA];
    __shared__ __align__(16) float Bs[2][BK][LDB];

    const int tid = threadIdx.x;
    const int tx = tid & 15;      // n microtile index
    const int ty = tid >> 4;      // m microtile index

    // Global->smem staging assignment: 2 float4 per array per thread
    const int a_row = tid >> 2;   // 0..63
    const int a_c4  = tid & 3;    // which float4 of the 16-wide k slab

    const float* aP0 = x  + ((size_t)blockIdx.x * BM + a_row) * DIM + a_c4 * 4;
    const float* aP1 = aP0 + (size_t)64 * DIM;
    const float* bP0 = Wg + (size_t)a_row * DIM + a_c4 * 4;   // n rows 0..63
    const float* bP1 = Wn + (size_t)a_row * DIM + a_c4 * 4;   // n rows 64..127

    unsigned long long c[8][4];   // 8 tokens x 8 n, packed as f32x2 pairs
#pragma unroll
    for (int i = 0; i < 8; ++i)
#pragma unroll
        for (int j = 0; j < 4; ++j) c[i][j] = 0ull;

    float4 ra0 = *(const float4*)aP0;
    float4 ra1 = *(const float4*)aP1;
    float4 rb0 = *(const float4*)bP0;
    float4 rb1 = *(const float4*)bP1;

#define STAGE_STORE(B_) do {                                              \
    int kc = a_c4 * 4;                                                    \
    As[B_][kc+0][a_row]    = ra0.x; As[B_][kc+1][a_row]    = ra0.y;       \
    As[B_][kc+2][a_row]    = ra0.z; As[B_][kc+3][a_row]    = ra0.w;       \
    As[B_][kc+0][a_row+64] = ra1.x; As[B_][kc+1][a_row+64] = ra1.y;       \
    As[B_][kc+2][a_row+64] = ra1.z; As[B_][kc+3][a_row+64] = ra1.w;       \
    Bs[B_][kc+0][a_row]    = rb0.x; Bs[B_][kc+1][a_row]    = rb0.y;       \
    Bs[B_][kc+2][a_row]    = rb0.z; Bs[B_][kc+3][a_row]    = rb0.w;       \
    Bs[B_][kc+0][a_row+64] = rb1.x; Bs[B_][kc+1][a_row+64] = rb1.y;       \
    Bs[B_][kc+2][a_row+64] = rb1.z; Bs[B_][kc+3][a_row+64] = rb1.w;       \
} while (0)

    STAGE_STORE(0);
    __syncthreads();

    const int nKB = DIM / BK;     // 128
    for (int kb = 0; kb < nKB; ++kb) {
        const int buf = kb & 1;
        if (kb + 1 < nKB) {
            const int off = (kb + 1) * BK;
            ra0 = *(const float4*)(aP0 + off);
            ra1 = *(const float4*)(aP1 + off);
            rb0 = *(const float4*)(bP0 + off);
            rb1 = *(const float4*)(bP1 + off);
        }
#pragma unroll
        for (int k = 0; k < BK; ++k) {
            float4 a0 = *(const float4*)&As[buf][k][ty * 8];
            float4 a1 = *(const float4*)&As[buf][k][ty * 8 + 4];
            float4 b0 = *(const float4*)&Bs[buf][k][tx * 8];
            float4 b1 = *(const float4*)&Bs[buf][k][tx * 8 + 4];
            unsigned long long bb[4];
            bb[0] = pk2(b0.x, b0.y); bb[1] = pk2(b0.z, b0.w);
            bb[2] = pk2(b1.x, b1.y); bb[3] = pk2(b1.z, b1.w);
            float av[8] = {a0.x, a0.y, a0.z, a0.w, a1.x, a1.y, a1.z, a1.w};
#pragma unroll
            for (int i = 0; i < 8; ++i) {
                unsigned long long aa = pk2(av[i], av[i]);
                fma2(c[i][0], aa, bb[0]);
                fma2(c[i][1], aa, bb[1]);
                fma2(c[i][2], aa, bb[2]);
                fma2(c[i][3], aa, bb[3]);
            }
        }
        if (kb + 1 < nKB) STAGE_STORE(buf ^ 1);
        __syncthreads();
    }
#undef STAGE_STORE

    const int token0 = blockIdx.x * BM + ty * 8;
    const int n0 = tx * 8;
#pragma unroll
    for (int i = 0; i < 8; ++i) {
        unsigned long long* dst =
            (unsigned long long*)(g_proj + (size_t)(token0 + i) * NTOT + n0);
        dst[0] = c[i][0]; dst[1] = c[i][1]; dst[2] = c[i][2]; dst[3] = c[i][3];
    }
}

// Stable softplus matching jax.nn.softplus = max(x,0) + log1p(exp(-|x|))
__device__ __forceinline__ float softplusf(float v) {
    return fmaxf(v, 0.f) + log1pf(expf(-fabsf(v)));
}

// ---- Kernel B: per-token epilogue (warp per token) ----------------------
__global__ __launch_bounds__(256) void epilogue_kernel(
    const float* __restrict__ raw_noise,
    const float* __restrict__ b_gate,
    float* __restrict__ out)
{
    const int lane = threadIdx.x & 31;
    const int warp = threadIdx.x >> 5;
    const int gw = blockIdx.x * EPI_WARPS + warp;
    const float bg0 = b_gate[lane];
    const float bg1 = b_gate[lane + 32];
    float psA = 0.f, psB = 0.f, cA = 0.f, cB = 0.f;   // per-lane expert partials
    const int t0 = gw * TOK_PER_WARP;

    for (int it = 0; it < TOK_PER_WARP; ++it) {
        const int t = t0 + it;
        const float* pr = g_proj + (size_t)t * NTOT;
        // noisy logits: lane owns experts e=lane and e=lane+32
        float v0 = pr[lane]      + bg0 +
                   raw_noise[(size_t)t * EXP + lane]      * (softplusf(pr[64 + lane]) + 0.01f);
        float v1 = pr[lane + 32] + bg1 +
                   raw_noise[(size_t)t * EXP + lane + 32] * (softplusf(pr[96 + lane]) + 0.01f);

        // local top-2 (tie -> lower index, matching jax.lax.top_k)
        float hv, lv; int hi, li;
        if (v0 >= v1) { hv = v0; hi = lane;      lv = v1; li = lane + 32; }
        else          { hv = v1; hi = lane + 32; lv = v0; li = lane;      }

        // warp butterfly top-2 merge (symmetric: all lanes converge)
#pragma unroll
        for (int off = 16; off > 0; off >>= 1) {
            float ohv = __shfl_xor_sync(0xffffffffu, hv, off);
            int   ohi = __shfl_xor_sync(0xffffffffu, hi, off);
            float olv = __shfl_xor_sync(0xffffffffu, lv, off);
            int   oli = __shfl_xor_sync(0xffffffffu, li, off);
            bool w1 = (hv > ohv) || (hv == ohv && hi < ohi);
            float whv = w1 ? hv : ohv;  int whi = w1 ? hi : ohi;
            float wlv = w1 ? lv : olv;  int wli = w1 ? li : oli;
            float lhv = w1 ? ohv : hv;  int lhi = w1 ? ohi : hi;
            bool s1 = (lhv > wlv) || (lhv == wlv && lhi < wli);
            hv = whv; hi = whi;
            lv = s1 ? lhv : wlv;  li = s1 ? lhi : wli;
        }

        // router softmax over all 64 noisy logits (aux loss p_e)
        float e0 = expf(v0 - hv), e1 = expf(v1 - hv);
        float s = e0 + e1;
#pragma unroll
        for (int off = 16; off > 0; off >>= 1)
            s += __shfl_xor_sync(0xffffffffu, s, off);
        float inv = 1.f / s;
        psA += e0 * inv;
        psB += e1 * inv;

        // softmax over the top-2
        float eb = expf(lv - hv);
        float p0 = 1.f / (1.f + eb);
        float p1 = eb / (1.f + eb);

        // indicator counts (p0 >= 0.5 always > 0; p1 may underflow to 0)
        if ((hi & 31) == lane)               { if (hi < 32) cA += 1.f; else cB += 1.f; }
        if (((li & 31) == lane) && p1 > 0.f) { if (li < 32) cA += 1.f; else cB += 1.f; }

        // scatter sparse row
        float o0 = (lane == hi)        ? p0 : ((lane == li)        ? p1 : 0.f);
        float o1 = ((lane + 32) == hi) ? p0 : (((lane + 32) == li) ? p1 : 0.f);
        out[(size_t)t * EXP + lane]      = o0;
        out[(size_t)t * EXP + lane + 32] = o1;
    }

    // deterministic per-block reduction of aux partials
    __shared__ float sm_ps[EPI_WARPS][EXP];
    __shared__ float sm_ct[EPI_WARPS][EXP];
    sm_ps[warp][lane]      = psA; sm_ps[warp][lane + 32] = psB;
    sm_ct[warp][lane]      = cA;  sm_ct[warp][lane + 32] = cB;
    __syncthreads();
    if (threadIdx.x < EXP) {
        float ps = 0.f, ct = 0.f;
#pragma unroll
        for (int w = 0; w < EPI_WARPS; ++w) {
            ps += sm_ps[w][threadIdx.x];
            ct += sm_ct[w][threadIdx.x];
        }
        g_psum[blockIdx.x * EXP + threadIdx.x] = ps;
        g_cnt [blockIdx.x * EXP + threadIdx.x] = ct;
    }
}

// ---- Kernel C: aux loss final reduction (deterministic) -----------------
__global__ void aux_kernel(float* __restrict__ out, int aux_idx) {
    const int e = threadIdx.x;   // 64 threads
    float ps = 0.f, ct = 0.f;
    for (int b = 0; b < EPI_BLOCKS; ++b) {
        ps += g_psum[b * EXP + e];
        ct += g_cnt [b * EXP + e];
    }
    float term = (ct * (1.f / (float)T_TOK)) * (ps * (1.f / (float)T_TOK));
#pragma unroll
    for (int off = 16; off > 0; off >>= 1)
        term += __shfl_xor_sync(0xffffffffu, term, off);
    __shared__ float sm[2];
    if ((e & 31) == 0) sm[e >> 5] = term;
    __syncthreads();
    if (e == 0) out[aux_idx] = (sm[0] + sm[1]) * (float)EXP;
}

extern "C" void kernel_launch(void* const* d_in, const int* in_sizes, int n_in,
                              void* d_out, int out_size) {
    (void)in_sizes; (void)n_in;
    const float* x  = (const float*)d_in[0];   // [16384, 2048]
    const float* rn = (const float*)d_in[1];   // [16384, 64]
    const float* Wg = (const float*)d_in[2];   // [64, 2048]
    const float* bg = (const float*)d_in[3];   // [64]
    const float* Wn = (const float*)d_in[4];   // [64, 2048]
    float* out = (float*)d_out;                // [16384*64 sparse] + [1 aux]

    gemm_kernel<<<T_TOK / BM, 256>>>(x, Wg, Wn);
    epilogue_kernel<<<EPI_BLOCKS, 256>>>(rn, bg, out);
    aux_kernel<<<1, EXP>>>(out, out_size - 1);
}